// round 5
// baseline (speedup 1.0000x reference)
#include <cuda_runtime.h>
#include <cfloat>

// x: (16, 256, 128, 128) fp32 NCHW.  y = 2 * revcummax_W( revcummax_H( x ) )
//
// One WARP per 128x128 image, no shared memory, no barriers.
// Lane owns 4 fixed columns (float4). Stream rows 127 -> 0:
//   run = per-column running max (the H reverse-cummax at row j),
//   then W reverse-cummax of run entirely in registers:
//     in-quad scan (3 fmax) + warp suffix-max over quad totals (5 shfl)
//     + exclusive shift (1 shfl), coalesced STG.128 of the final row.
// Rows are prefetched 8 deep -> MLP=8 per warp; the only cross-row serial
// dependency is the 4-cycle f4max chain.

#define IMG_W 128
#define IMG_H 128
#define UNROLL 8
#define WARPS_PER_CTA 8

__device__ __forceinline__ float4 f4max(float4 a, float4 b) {
    a.x = fmaxf(a.x, b.x); a.y = fmaxf(a.y, b.y);
    a.z = fmaxf(a.z, b.z); a.w = fmaxf(a.w, b.w);
    return a;
}

__global__ void __launch_bounds__(32 * WARPS_PER_CTA)
tlc_kernel(const float* __restrict__ x, float* __restrict__ y) {
    const int lane = threadIdx.x & 31;
    const int wid  = threadIdx.x >> 5;
    const long long img = (long long)blockIdx.x * WARPS_PER_CTA + wid;
    const long long base = img * (IMG_H * IMG_W);

    const float4* __restrict__ xin4  = (const float4*)(x + base);
    float4*       __restrict__ yout4 = (float4*)(y + base);

    // prefetch rows 127 .. 127-UNROLL+1
    float4 buf[UNROLL];
    #pragma unroll
    for (int u = 0; u < UNROLL; ++u)
        buf[u] = xin4[(IMG_H - 1 - u) * 32 + lane];

    float4 run = make_float4(-FLT_MAX, -FLT_MAX, -FLT_MAX, -FLT_MAX);

    for (int jb = IMG_H - 1; jb >= 0; jb -= UNROLL) {
        #pragma unroll
        for (int u = 0; u < UNROLL; ++u) {
            const int j  = jb - u;
            float4 v = buf[u];
            const int jp = j - UNROLL;
            if (jp >= 0) buf[u] = xin4[jp * 32 + lane];   // prefetch ahead

            // H reverse-cummax: per-column running max
            run = f4max(run, v);

            // W reverse-cummax of this row, in registers
            float4 w = run;
            w.z = fmaxf(w.z, w.w);
            w.y = fmaxf(w.y, w.z);
            w.x = fmaxf(w.x, w.y);

            // inclusive suffix-max of quad totals across lanes
            float s = w.x;
            #pragma unroll
            for (int d = 1; d < 32; d <<= 1) {
                float o = __shfl_down_sync(0xffffffffu, s, d);
                if (lane + d < 32) s = fmaxf(s, o);
            }
            // exclusive: value from lane+1
            float e = __shfl_down_sync(0xffffffffu, s, 1);
            if (lane == 31) e = -FLT_MAX;

            float4 o;
            o.x = 2.0f * fmaxf(w.x, e);
            o.y = 2.0f * fmaxf(w.y, e);
            o.z = 2.0f * fmaxf(w.z, e);
            o.w = 2.0f * fmaxf(w.w, e);
            yout4[j * 32 + lane] = o;
        }
    }
}

extern "C" void kernel_launch(void* const* d_in, const int* in_sizes, int n_in,
                              void* d_out, int out_size) {
    const float* x = (const float*)d_in[0];
    float* y = (float*)d_out;
    const int n_imgs = in_sizes[0] / (IMG_H * IMG_W);          // 4096
    const int n_ctas = n_imgs / WARPS_PER_CTA;                 // 512
    tlc_kernel<<<n_ctas, 32 * WARPS_PER_CTA>>>(x, y);
}

// round 6
// speedup vs baseline: 1.0340x; 1.0340x over previous
#include <cuda_runtime.h>
#include <cfloat>

// x: (16, 256, 128, 128) fp32 NCHW.  y = 2 * revcummax_W( revcummax_H( x ) )
//
// One WARP per 128x128 image, zero smem, zero barriers.
// Lane owns 4 fixed columns (float4). Stream rows 127 -> 0:
//   run = per-column running max (H reverse-cummax at row j), then the W
//   reverse-cummax of run in registers: in-quad scan (3 fmax) + warp
//   suffix-max over quad totals (5 shfl, predicate-free: out-of-range
//   shfl_down returns own value and fmax(s,s)=s) + exclusive shift.
// 4 warps/CTA -> grid 1024 = 6.92 CTAs/SM: wave-quantization tail ~1%
// (vs ~16% at grid 512 with 8 warps/CTA, the R5 regression).

#define IMG_W 128
#define IMG_H 128
#define UNROLL 8
#define WARPS_PER_CTA 4

__device__ __forceinline__ float4 f4max(float4 a, float4 b) {
    a.x = fmaxf(a.x, b.x); a.y = fmaxf(a.y, b.y);
    a.z = fmaxf(a.z, b.z); a.w = fmaxf(a.w, b.w);
    return a;
}

__global__ void __launch_bounds__(32 * WARPS_PER_CTA)
tlc_kernel(const float* __restrict__ x, float* __restrict__ y) {
    const int lane = threadIdx.x & 31;
    const int wid  = threadIdx.x >> 5;
    const long long img = (long long)blockIdx.x * WARPS_PER_CTA + wid;
    const long long base = img * (IMG_H * IMG_W);

    const float4* __restrict__ xin4  = (const float4*)(x + base);
    float4*       __restrict__ yout4 = (float4*)(y + base);

    // prefetch rows 127 .. 127-UNROLL+1
    float4 buf[UNROLL];
    #pragma unroll
    for (int u = 0; u < UNROLL; ++u)
        buf[u] = xin4[(IMG_H - 1 - u) * 32 + lane];

    float4 run = make_float4(-FLT_MAX, -FLT_MAX, -FLT_MAX, -FLT_MAX);

    for (int jb = IMG_H - 1; jb >= 0; jb -= UNROLL) {
        #pragma unroll
        for (int u = 0; u < UNROLL; ++u) {
            const int j  = jb - u;
            float4 v = buf[u];
            const int jp = j - UNROLL;
            if (jp >= 0) buf[u] = xin4[jp * 32 + lane];   // prefetch ahead

            // H reverse-cummax: per-column running max
            run = f4max(run, v);

            // W reverse-cummax of this row, in registers
            float4 w = run;
            w.z = fmaxf(w.z, w.w);
            w.y = fmaxf(w.y, w.z);
            w.x = fmaxf(w.x, w.y);

            // inclusive suffix-max of quad totals across lanes.
            // out-of-range shfl_down returns own value; fmax(s,s)=s -> no guard.
            float s = w.x;
            #pragma unroll
            for (int d = 1; d < 32; d <<= 1) {
                float o = __shfl_down_sync(0xffffffffu, s, d);
                s = fmaxf(s, o);
            }
            // exclusive: value from lane+1 (lane 31: neutral)
            float e = __shfl_down_sync(0xffffffffu, s, 1);
            if (lane == 31) e = -FLT_MAX;

            float4 o;
            o.x = 2.0f * fmaxf(w.x, e);
            o.y = 2.0f * fmaxf(w.y, e);
            o.z = 2.0f * fmaxf(w.z, e);
            o.w = 2.0f * fmaxf(w.w, e);
            yout4[j * 32 + lane] = o;
        }
    }
}

extern "C" void kernel_launch(void* const* d_in, const int* in_sizes, int n_in,
                              void* d_out, int out_size) {
    const float* x = (const float*)d_in[0];
    float* y = (float*)d_out;
    const int n_imgs = in_sizes[0] / (IMG_H * IMG_W);          // 4096
    const int n_ctas = n_imgs / WARPS_PER_CTA;                 // 1024
    tlc_kernel<<<n_ctas, 32 * WARPS_PER_CTA>>>(x, y);
}

// round 7
// speedup vs baseline: 1.0394x; 1.0052x over previous
#include <cuda_runtime.h>
#include <cfloat>

// x: (16, 256, 128, 128) fp32 NCHW.  y = 2 * revcummax_W( revcummax_H( x ) )
//
// One WARP per 128x128 image, zero smem, zero barriers.
// Lane owns 4 fixed columns (float4). Stream rows 127 -> 0:
//   run = per-column running max (H reverse-cummax at row j), then the W
//   reverse-cummax of run in registers: in-quad scan (3 fmax) + warp
//   suffix-max over quad totals (5 shfl, predicate-free) + exclusive shift.
// R7 delta: __ldcs / __stcs streaming hints (zero-reuse workload; keep the
// lines evict-first in L2 so reads and writes stop fighting for fill).

#define IMG_W 128
#define IMG_H 128
#define UNROLL 8
#define WARPS_PER_CTA 4

__device__ __forceinline__ float4 f4max(float4 a, float4 b) {
    a.x = fmaxf(a.x, b.x); a.y = fmaxf(a.y, b.y);
    a.z = fmaxf(a.z, b.z); a.w = fmaxf(a.w, b.w);
    return a;
}

__global__ void __launch_bounds__(32 * WARPS_PER_CTA)
tlc_kernel(const float* __restrict__ x, float* __restrict__ y) {
    const int lane = threadIdx.x & 31;
    const int wid  = threadIdx.x >> 5;
    const long long img = (long long)blockIdx.x * WARPS_PER_CTA + wid;
    const long long base = img * (IMG_H * IMG_W);

    const float4* __restrict__ xin4  = (const float4*)(x + base);
    float4*       __restrict__ yout4 = (float4*)(y + base);

    // prefetch rows 127 .. 127-UNROLL+1 (streaming loads)
    float4 buf[UNROLL];
    #pragma unroll
    for (int u = 0; u < UNROLL; ++u)
        buf[u] = __ldcs(&xin4[(IMG_H - 1 - u) * 32 + lane]);

    float4 run = make_float4(-FLT_MAX, -FLT_MAX, -FLT_MAX, -FLT_MAX);

    for (int jb = IMG_H - 1; jb >= 0; jb -= UNROLL) {
        #pragma unroll
        for (int u = 0; u < UNROLL; ++u) {
            const int j  = jb - u;
            float4 v = buf[u];
            const int jp = j - UNROLL;
            if (jp >= 0) buf[u] = __ldcs(&xin4[jp * 32 + lane]); // prefetch

            // H reverse-cummax: per-column running max
            run = f4max(run, v);

            // W reverse-cummax of this row, in registers
            float4 w = run;
            w.z = fmaxf(w.z, w.w);
            w.y = fmaxf(w.y, w.z);
            w.x = fmaxf(w.x, w.y);

            // inclusive suffix-max of quad totals across lanes.
            // out-of-range shfl_down returns own value; fmax(s,s)=s -> no guard.
            float s = w.x;
            #pragma unroll
            for (int d = 1; d < 32; d <<= 1) {
                float o = __shfl_down_sync(0xffffffffu, s, d);
                s = fmaxf(s, o);
            }
            // exclusive: value from lane+1 (lane 31: neutral)
            float e = __shfl_down_sync(0xffffffffu, s, 1);
            if (lane == 31) e = -FLT_MAX;

            float4 o;
            o.x = 2.0f * fmaxf(w.x, e);
            o.y = 2.0f * fmaxf(w.y, e);
            o.z = 2.0f * fmaxf(w.z, e);
            o.w = 2.0f * fmaxf(w.w, e);
            __stcs(&yout4[j * 32 + lane], o);
        }
    }
}

extern "C" void kernel_launch(void* const* d_in, const int* in_sizes, int n_in,
                              void* d_out, int out_size) {
    const float* x = (const float*)d_in[0];
    float* y = (float*)d_out;
    const int n_imgs = in_sizes[0] / (IMG_H * IMG_W);          // 4096
    const int n_ctas = n_imgs / WARPS_PER_CTA;                 // 1024
    tlc_kernel<<<n_ctas, 32 * WARPS_PER_CTA>>>(x, y);
}

// round 11
// speedup vs baseline: 1.0397x; 1.0003x over previous
#include <cuda_runtime.h>
#include <cfloat>

// x: (16, 256, 128, 128) fp32 NCHW.  y = 2 * revcummax_W( revcummax_H( x ) )
//
// One WARP per 128x128 image, zero smem, zero barriers.
// Lane owns 4 fixed columns (float4). Stream rows 127 -> 0:
//   run = per-column running max (H reverse-cummax at row j), then the W
//   reverse-cummax of run in registers: in-quad scan (3 fmax) + warp
//   suffix-max over quad totals (5 shfl, predicate-free) + exclusive shift.
// R8 delta: 1 warp per CTA -> grid 4096 fine-grained CTAs. Bench times
// steady-state graph replay where coarse single-wave grids (R5-R7) pay the
// slowest-SM spread (~9-10us bench/ncu gap); fine CTAs work-steal it away
// (R4's gap was 3.4us). Inner code identical to R7.

#define IMG_W 128
#define IMG_H 128
#define UNROLL 8
#define WARPS_PER_CTA 1

__device__ __forceinline__ float4 f4max(float4 a, float4 b) {
    a.x = fmaxf(a.x, b.x); a.y = fmaxf(a.y, b.y);
    a.z = fmaxf(a.z, b.z); a.w = fmaxf(a.w, b.w);
    return a;
}

__global__ void __launch_bounds__(32 * WARPS_PER_CTA)
tlc_kernel(const float* __restrict__ x, float* __restrict__ y) {
    const int lane = threadIdx.x & 31;
    const long long img = (long long)blockIdx.x;
    const long long base = img * (IMG_H * IMG_W);

    const float4* __restrict__ xin4  = (const float4*)(x + base);
    float4*       __restrict__ yout4 = (float4*)(y + base);

    // prefetch rows 127 .. 127-UNROLL+1 (streaming loads)
    float4 buf[UNROLL];
    #pragma unroll
    for (int u = 0; u < UNROLL; ++u)
        buf[u] = __ldcs(&xin4[(IMG_H - 1 - u) * 32 + lane]);

    float4 run = make_float4(-FLT_MAX, -FLT_MAX, -FLT_MAX, -FLT_MAX);

    for (int jb = IMG_H - 1; jb >= 0; jb -= UNROLL) {
        #pragma unroll
        for (int u = 0; u < UNROLL; ++u) {
            const int j  = jb - u;
            float4 v = buf[u];
            const int jp = j - UNROLL;
            if (jp >= 0) buf[u] = __ldcs(&xin4[jp * 32 + lane]); // prefetch

            // H reverse-cummax: per-column running max
            run = f4max(run, v);

            // W reverse-cummax of this row, in registers
            float4 w = run;
            w.z = fmaxf(w.z, w.w);
            w.y = fmaxf(w.y, w.z);
            w.x = fmaxf(w.x, w.y);

            // inclusive suffix-max of quad totals across lanes.
            // out-of-range shfl_down returns own value; fmax(s,s)=s -> no guard.
            float s = w.x;
            #pragma unroll
            for (int d = 1; d < 32; d <<= 1) {
                float o = __shfl_down_sync(0xffffffffu, s, d);
                s = fmaxf(s, o);
            }
            // exclusive: value from lane+1 (lane 31: neutral)
            float e = __shfl_down_sync(0xffffffffu, s, 1);
            if (lane == 31) e = -FLT_MAX;

            float4 o;
            o.x = 2.0f * fmaxf(w.x, e);
            o.y = 2.0f * fmaxf(w.y, e);
            o.z = 2.0f * fmaxf(w.z, e);
            o.w = 2.0f * fmaxf(w.w, e);
            __stcs(&yout4[j * 32 + lane], o);
        }
    }
}

extern "C" void kernel_launch(void* const* d_in, const int* in_sizes, int n_in,
                              void* d_out, int out_size) {
    const float* x = (const float*)d_in[0];
    float* y = (float*)d_out;
    const int n_imgs = in_sizes[0] / (IMG_H * IMG_W);          // 4096
    tlc_kernel<<<n_imgs, 32 * WARPS_PER_CTA>>>(x, y);
}

// round 12
// speedup vs baseline: 1.1316x; 1.0883x over previous
#include <cuda_runtime.h>
#include <cfloat>

// x: (16, 256, 128, 128) fp32 NCHW.  y = 2 * revcummax_W( revcummax_H( x ) )
//
// One CTA (256 threads) per image, FOUR 32-row phases bottom-to-top.
// Per-column running max carried across phases in double-buffered colmax[].
// Tile 32 x 132 fp32 (16.9 KB) -> target 8 CTAs/SM (multi-wave schedule:
// ~1184 resident, 4096 CTAs = 3.5 waves; single-wave warp-per-image designs
// pay the slowest-SM spread in bench replay, R5-R11 evidence).
// H-scan: 16-row segment per thread in smem. W-scan: registers + shuffles,
// fused with the store (quad scan + warp suffix-max + exclusive shift).

#define IMG_W 128
#define IMG_H 128
#define PH 32                 // rows per phase
#define NPH 4
#define PITCH 132             // 128 + 4 -> float4-aligned rows, conflict-free

__device__ __forceinline__ float4 f4max(float4 a, float4 b) {
    a.x = fmaxf(a.x, b.x); a.y = fmaxf(a.y, b.y);
    a.z = fmaxf(a.z, b.z); a.w = fmaxf(a.w, b.w);
    return a;
}

__global__ void __launch_bounds__(256, 8)
tlc_kernel(const float* __restrict__ x, float* __restrict__ y) {
    __shared__ float tile[PH * PITCH];     // 16896 B
    __shared__ float colmax[2][IMG_W];     // 1024 B, double-buffered carry

    const int t    = threadIdx.x;
    const int lane = t & 31;
    const int wid  = t >> 5;               // 0..7
    const int col  = t & 127;              // H-scan column
    const int hseg = t >> 7;               // 0 or 1 (16-row segment)
    const long long base = (long long)blockIdx.x * (IMG_H * IMG_W);

    // init carry buffer 0 (phase 3 has nothing below it)
    if (t < IMG_W) colmax[0][t] = -FLT_MAX;
    // (visibility guaranteed by the first load-phase __syncthreads)

    #pragma unroll
    for (int i = 0; i < NPH; ++i) {
        const int phase = NPH - 1 - i;                 // 3,2,1,0
        const int cur = i & 1, nxt = cur ^ 1;
        const float4* __restrict__ xin4 =
            (const float4*)(x + base + phase * (PH * IMG_W));
        float4* __restrict__ yout4 =
            (float4*)(y + base + phase * (PH * IMG_W));

        // ---- load 32x128: warp owns 4 rows, float4 LDG -> STS.128 ----
        #pragma unroll
        for (int k = 0; k < 4; ++k) {
            int r = wid * 4 + k;
            float4 v = __ldcs(&xin4[r * 32 + lane]);
            *(float4*)&tile[r * PITCH + 4 * lane] = v;
        }
        __syncthreads();

        // ---- H-scan: 16-row segment-local reverse cummax per column ----
        {
            const int r0 = hseg * 16;
            float run = -FLT_MAX;
            #pragma unroll
            for (int j = 15; j >= 0; --j) {
                int idx = (r0 + j) * PITCH + col;
                run = fmaxf(run, tile[idx]);
                tile[idx] = run;
            }
        }
        __syncthreads();

        // ---- W pass fused with store; tile + colmax[cur] READ-ONLY ----
        {
            // per-column folds, loaded once per warp
            float4 cm = *(const float4*)&colmax[cur][4 * lane];
            float4 t16 = *(const float4*)&tile[16 * PITCH + 4 * lane]; // seg1 total
            float4 f0 = f4max(cm, t16);   // fold for rows 0..15
            #pragma unroll
            for (int k = 0; k < 4; ++k) {
                int r = wid * 4 + k;
                float4 v = *(const float4*)&tile[r * PITCH + 4 * lane];
                v = f4max(v, (r < 16) ? f0 : cm);

                // in-quad reverse cummax
                v.z = fmaxf(v.z, v.w);
                v.y = fmaxf(v.y, v.z);
                v.x = fmaxf(v.x, v.y);

                // warp suffix-max of quad totals (predicate-free), excl shift
                float s = v.x;
                #pragma unroll
                for (int d = 1; d < 32; d <<= 1)
                    s = fmaxf(s, __shfl_down_sync(0xffffffffu, s, d));
                float e = __shfl_down_sync(0xffffffffu, s, 1);
                if (lane == 31) e = -FLT_MAX;

                float4 o;
                o.x = 2.0f * fmaxf(v.x, e);
                o.y = 2.0f * fmaxf(v.y, e);
                o.z = 2.0f * fmaxf(v.z, e);
                o.w = 2.0f * fmaxf(v.w, e);
                __stcs(&yout4[r * 32 + lane], o);
            }
        }

        // ---- carry update into the OTHER buffer (no extra sync needed) ----
        if (t < IMG_W) {
            float tot = fmaxf(tile[0 * PITCH + t], tile[16 * PITCH + t]);
            colmax[nxt][t] = fmaxf(colmax[cur][t], tot);
        }
        __syncthreads();   // tile/colmax stable before next phase's load
    }
}

extern "C" void kernel_launch(void* const* d_in, const int* in_sizes, int n_in,
                              void* d_out, int out_size) {
    const float* x = (const float*)d_in[0];
    float* y = (float*)d_out;
    const int n_imgs = in_sizes[0] / (IMG_H * IMG_W);   // 4096
    tlc_kernel<<<n_imgs, 256>>>(x, y);
}